// round 15
// baseline (speedup 1.0000x reference)
#include <cuda_runtime.h>
#include <cuda_fp16.h>
#include <math.h>
#include <stdint.h>

#define Bb 2
#define Hh 16
#define Nn 2048
#define Dd 128
#define NP 7
#define BH (Bb*Hh)

// ---------------- device scratch ----------------
__device__ int g_qhash[BH*Nn];
__device__ int g_khash[BH*Nn];
__device__ int g_sidx[BH*Nn];
__device__ int g_keep[64];
__device__ __align__(16) unsigned char g_khi[(size_t)BH*Nn*256];
__device__ __align__(16) unsigned char g_vhi[(size_t)BH*Nn*256];

// ---------------- helpers ----------------
__device__ __forceinline__ uint32_t smem_u32(const void* p) {
    uint32_t a;
    asm("{ .reg .u64 t; cvta.to.shared.u64 t, %1; cvt.u32.u64 %0, t; }" : "=r"(a) : "l"(p));
    return a;
}
__device__ __forceinline__ uint32_t pack2h(float a, float b) {
    __half2 h = __floats2half2_rn(a, b);
    return *(uint32_t*)&h;
}
__device__ __forceinline__ void mma(float d[4], const uint32_t a[4], uint32_t b0, uint32_t b1) {
    asm volatile("mma.sync.aligned.m16n8k16.row.col.f32.f16.f16.f32 "
        "{%0,%1,%2,%3},{%4,%5,%6,%7},{%8,%9},{%0,%1,%2,%3};"
        : "+f"(d[0]), "+f"(d[1]), "+f"(d[2]), "+f"(d[3])
        : "r"(a[0]), "r"(a[1]), "r"(a[2]), "r"(a[3]), "r"(b0), "r"(b1));
}
__device__ __forceinline__ void ldsm4(uint32_t r[4], uint32_t a) {
    asm volatile("ldmatrix.sync.aligned.m8n8.x4.shared.b16 {%0,%1,%2,%3},[%4];"
        : "=r"(r[0]), "=r"(r[1]), "=r"(r[2]), "=r"(r[3]) : "r"(a));
}
__device__ __forceinline__ void ldsm4t(uint32_t r[4], uint32_t a) {
    asm volatile("ldmatrix.sync.aligned.m8n8.x4.trans.shared.b16 {%0,%1,%2,%3},[%4];"
        : "=r"(r[0]), "=r"(r[1]), "=r"(r[2]), "=r"(r[3]) : "r"(a));
}
#define CPA(dst, src) asm volatile("cp.async.cg.shared.global [%0],[%1],16;" :: "r"(dst), "l"(src))
#define CPC()  asm volatile("cp.async.commit_group;" ::: "memory")
#define CPW(n) asm volatile("cp.async.wait_group %0;" :: "n"(n) : "memory")

// ---------------- LSH hash (also zero-inits g_keep) ----------------
__global__ void hash_kernel(const float* __restrict__ q, const float* __restrict__ k,
                            const float* __restrict__ pd) {
    if (blockIdx.x == 0 && threadIdx.x < 64) g_keep[threadIdx.x] = 0;
    __shared__ float pds[Dd*NP];
    for (int i = threadIdx.x; i < Dd*NP; i += blockDim.x) pds[i] = pd[i];
    __syncthreads();
    int warp = threadIdx.x >> 5, lane = threadIdx.x & 31;
    int gid = blockIdx.x * 8 + warp;
    int t = gid >> 16, row = gid & 65535;
    const float* src = t ? k : q;
    int n = row & (Nn-1), h = (row >> 11) & (Hh-1), b = row >> 15;
    float4 x = ((const float4*)(src + ((size_t)(b*Nn+n)*Hh + h)*Dd))[lane];
    int d0 = lane * 4;
    float acc[NP];
    #pragma unroll
    for (int p = 0; p < NP; p++)
        acc[p] = x.x*pds[(d0+0)*NP+p] + x.y*pds[(d0+1)*NP+p]
               + x.z*pds[(d0+2)*NP+p] + x.w*pds[(d0+3)*NP+p];
    #pragma unroll
    for (int p = 0; p < NP; p++)
        #pragma unroll
        for (int o = 16; o; o >>= 1) acc[p] += __shfl_xor_sync(0xffffffffu, acc[p], o);
    if (lane == 0) {
        int bin = 0;
        #pragma unroll
        for (int p = 0; p < NP; p++) bin |= ((acc[p] > 0.f) ? 1 : 0) << p;
        (t ? g_khash : g_qhash)[row] = bin ^ (bin >> 1);
    }
}

// ---------------- stable counting sort per (b,h) + fused keep ----------------
__global__ void sort_kernel() {
    __shared__ int hs[Nn];
    __shared__ int cnt[128];
    __shared__ int ks[64];
    int bh = blockIdx.x, base = bh * Nn;
    for (int i = threadIdx.x; i < Nn; i += 128) hs[i] = g_qhash[base + i];
    if (threadIdx.x < 64) ks[threadIdx.x] = 0;
    __syncthreads();
    int key = threadIdx.x, c = 0;
    for (int i = 0; i < Nn; i++) c += (hs[i] == key);
    cnt[key] = c;
    __syncthreads();
    int off = 0;
    for (int j = 0; j < key; j++) off += cnt[j];
    for (int i = 0; i < Nn; i++)
        if (hs[i] == key) {
            g_sidx[base + off] = i;
            if (key == g_khash[base + off]) ks[off >> 5] = 1;
            off++;
        }
    __syncthreads();
    if (threadIdx.x < 64 && ks[threadIdx.x]) atomicOr(&g_keep[threadIdx.x], 1);
}

// ---------------- K/V prep: single fp16 images ----------------
__global__ void kvprep(const float* __restrict__ kg, const float* __restrict__ vg) {
    int idx = blockIdx.x * 256 + threadIdx.x;        // 2*BH*Nn*16
    int c = idx & 15;
    int row = (idx >> 4) & (Nn-1);
    int bh  = (idx >> 15) & (BH-1);
    int isv = idx >> 20;
    int h = bh & 15, b = bh >> 4;
    const float* src = isv ? vg : kg;
    float kp = (isv || g_keep[h*4 + (row >> 9)]) ? 1.f : 0.f;
    const float4* sp = (const float4*)(src + ((size_t)(b*Nn+row)*Hh + h)*Dd) + c*2;
    float4 x0 = sp[0], x1 = sp[1];
    uint4 hv;
    hv.x = pack2h(x0.x*kp, x0.y*kp);
    hv.y = pack2h(x0.z*kp, x0.w*kp);
    hv.z = pack2h(x1.x*kp, x1.y*kp);
    hv.w = pack2h(x1.z*kp, x1.w*kp);
    size_t off = ((size_t)(bh*Nn + row))*256 + (size_t)((c ^ (row&7)) << 4);
    *(uint4*)((isv ? g_vhi : g_khi) + off) = hv;
}

// ---------------- HMMA flash attention ----------------
// fp16, single Q/K/P images; Q pre-scaled by D^-0.5*log2(e); p = exp2(s)
// via ex2.approx.f16x2; l = P @ ones on the tensor core.
// Round-15 changes: (a) per-jp S accumulation with double-buffered K
// fragments (breaks ldsm->mma dependency, -24 regs), (b) double-buffered
// V fragments in PV, (c) keep-skip: keep==0 tiles skip all S MMAs/LDSM
// (K tile is all zeros -> s=0 exactly).
#define STAGE   65536           /* KHI 32K | V 32K */
#define OFF_V   32768
#define SMEMT   131072
#define ONES2   0x3C003C00u     /* fp16x2 {1,1} */

__global__ void __launch_bounds__(256, 1)
attn_kernel(const float* __restrict__ qg, float* __restrict__ out) {
    extern __shared__ __align__(16) unsigned char dsm[];
    uint32_t sb = smem_u32(dsm);
    int tid = threadIdx.x, warp = tid >> 5, lane = tid & 31;
    int qt = 15 - (int)blockIdx.x, h = blockIdx.y, b = blockIdx.z;
    int bh = b*Hh + h;

    // ---- stage Q (gathered rows, pre-scaled by sc*log2e, single fp16)
    {
        const float sc = 0.12751741f;   // 128^-0.5 * log2(e)
        #pragma unroll
        for (int it = 0; it < 8; it++) {
            int i = tid + it*256;
            int row = i >> 4, c = i & 15;
            int n = g_sidx[bh*Nn + qt*128 + row];
            const float4* qp = (const float4*)(qg + ((size_t)(b*Nn+n)*Hh + h)*Dd) + c*2;
            float4 x0 = qp[0], x1 = qp[1];
            uint4 hv;
            hv.x = pack2h(x0.x*sc, x0.y*sc);
            hv.y = pack2h(x0.z*sc, x0.w*sc);
            hv.z = pack2h(x1.x*sc, x1.y*sc);
            hv.w = pack2h(x1.z*sc, x1.w*sc);
            *(uint4*)(dsm + row*256 + ((c ^ (row&7)) << 4)) = hv;
        }
    }
    __syncthreads();

    // ---- extract Q fragments (A operand, 8 k-steps)
    uint32_t qh[8][4];
    {
        int qrow = 16*warp + (lane & 15);
        int cbit = lane >> 4, rsw = qrow & 7;
        uint32_t qb = sb + qrow*256;
        #pragma unroll
        for (int kk = 0; kk < 8; kk++)
            ldsm4(qh[kk], qb + (((2*kk + cbit) ^ rsw) << 4));
    }
    __syncthreads();

    size_t gbase = (size_t)(bh*Nn) * 256;

    // ---- prologue: stage 0 <- key tile 0 (128 keys: K 32KB, V 32KB)
    #pragma unroll
    for (int i2 = 0; i2 < 8; i2++) {
        int i = tid + i2*256;
        CPA(sb + i*16,         g_khi + gbase + i*16);
        CPA(sb + OFF_V + i*16, g_vhi + gbase + i*16);
    }
    CPC();

    float o[16][4];
    #pragma unroll
    for (int j = 0; j < 16; j++)
        #pragma unroll
        for (int e = 0; e < 4; e++) o[j][e] = 0.f;
    float lfr[4] = {0.f, 0.f, 0.f, 0.f};   // l = P @ ones (tensor-core)

    int keyl = lane & 15, ksw = keyl & 7, cbit = lane >> 4;
    int grA = qt*128 + 16*warp + (lane >> 2), grB = grA + 8;

    for (int kt = 0; kt <= qt; kt++) {
        CPW(0);
        __syncthreads();

        // prefetch next 128-key tile into the other stage
        if (kt < qt) {
            uint32_t st = sb + ((kt+1)&1)*STAGE;
            size_t gs = gbase + (size_t)(kt+1)*32768;
            #pragma unroll
            for (int i2 = 0; i2 < 8; i2++) {
                int i = tid + i2*256;
                CPA(st + i*16,         g_khi + gs + i*16);
                CPA(st + OFF_V + i*16, g_vhi + gs + i*16);
            }
            CPC();
        }

        bool dg = (kt == qt);
        int kp = g_keep[h*4 + (kt >> 2)];   // uniform per tile
        uint32_t stage = sb + (kt&1)*STAGE;

        #pragma unroll
        for (int sub = 0; sub < 2; sub++) {
            uint32_t stK = stage + sub*16384 + keyl*256;
            uint32_t stV = stage + OFF_V + sub*16384 + keyl*256;

            uint32_t phi[4][4];

            // ---- per jp-tile (16 keys): S accumulate + fused exp2/pack
            #pragma unroll
            for (int jp = 0; jp < 4; jp++) {
                float s4[2][4];
                #pragma unroll
                for (int jj = 0; jj < 2; jj++)
                    #pragma unroll
                    for (int e = 0; e < 4; e++) s4[jj][e] = 0.f;

                if (kp) {   // keep==0 -> K tile all zeros -> s stays 0
                    uint32_t kb[2][4];
                    ldsm4(kb[0], stK + jp*4096 + ((cbit ^ ksw) << 4));
                    #pragma unroll
                    for (int kk = 0; kk < 8; kk++) {
                        if (kk < 7)
                            ldsm4(kb[(kk+1)&1],
                                  stK + jp*4096 + (((2*(kk+1) + cbit) ^ ksw) << 4));
                        mma(s4[0], qh[kk], kb[kk&1][0], kb[kk&1][2]);
                        mma(s4[1], qh[kk], kb[kk&1][1], kb[kk&1][3]);
                    }
                }

                #pragma unroll
                for (int u = 0; u < 4; u++) {
                    int jj = u >> 1;
                    float a0 = s4[jj][(u & 1) ? 2 : 0];
                    float a1 = s4[jj][(u & 1) ? 3 : 1];
                    if (dg) {
                        int gc = kt*128 + sub*64 + 8*(2*jp+jj) + 2*(lane & 3);
                        int gr = (u & 1) ? grB : grA;
                        if (gc     > gr) a0 = -60000.f;   // exp2 -> 0
                        if (gc + 1 > gr) a1 = -60000.f;
                    }
                    uint32_t hh = pack2h(a0, a1);
                    asm("ex2.approx.f16x2 %0, %1;" : "=r"(phi[jp][u]) : "r"(hh));
                }
            }

            // ---- l += P @ ones ; O += P * V (V fragments double-buffered)
            {
                uint32_t vb[2][4];
                ldsm4t(vb[0], stV + ((cbit ^ ksw) << 4));
                #pragma unroll
                for (int t = 0; t < 32; t++) {
                    if (t < 31) {
                        int tn = t + 1;
                        ldsm4t(vb[tn&1], stV + (tn>>3)*4096
                               + (((2*(tn&7) + cbit) ^ ksw) << 4));
                    }
                    int k2 = t >> 3, jpv = t & 7;
                    if (jpv == 0) mma(lfr, phi[k2], ONES2, ONES2);
                    mma(o[2*jpv],   phi[k2], vb[t&1][0], vb[t&1][1]);
                    mma(o[2*jpv+1], phi[k2], vb[t&1][2], vb[t&1][3]);
                }
            }
        }
    }

    // ---- epilogue: normalize (l already per-row in lfr), scatter
    float iA = 1.f / lfr[0], iB = 1.f / lfr[2];
    int nA = g_sidx[bh*Nn + qt*128 + 16*warp + (lane >> 2)];
    int nB = g_sidx[bh*Nn + qt*128 + 16*warp + (lane >> 2) + 8];
    float* opA = out + ((size_t)(b*Nn+nA)*Hh + h)*Dd;
    float* opB = out + ((size_t)(b*Nn+nB)*Hh + h)*Dd;
    #pragma unroll
    for (int j = 0; j < 16; j++) {
        int col = 8*j + 2*(lane & 3);
        *(float2*)(opA + col) = make_float2(o[j][0]*iA, o[j][1]*iA);
        *(float2*)(opB + col) = make_float2(o[j][2]*iB, o[j][3]*iB);
    }
}

// ---------------- launch ----------------
extern "C" void kernel_launch(void* const* d_in, const int* in_sizes, int n_in,
                              void* d_out, int out_size) {
    const float* q  = (const float*)d_in[0];
    const float* k  = (const float*)d_in[1];
    const float* v  = (const float*)d_in[2];
    const float* pd = (const float*)d_in[3];
    float* out = (float*)d_out;

    hash_kernel<<<16384, 256>>>(q, k, pd);
    sort_kernel<<<BH, 128>>>();
    kvprep<<<8192, 256>>>(k, v);
    cudaFuncSetAttribute(attn_kernel, cudaFuncAttributeMaxDynamicSharedMemorySize, SMEMT);
    attn_kernel<<<dim3(16, Hh, Bb), 256, SMEMT>>>(q, out);
}

// round 16
// speedup vs baseline: 1.5082x; 1.5082x over previous
#include <cuda_runtime.h>
#include <cuda_fp16.h>
#include <math.h>
#include <stdint.h>

#define Bb 2
#define Hh 16
#define Nn 2048
#define Dd 128
#define NP 7
#define BH (Bb*Hh)

// ---------------- device scratch ----------------
__device__ int g_qhash[BH*Nn];
__device__ int g_khash[BH*Nn];
__device__ int g_sidx[BH*Nn];
__device__ int g_keep[64];
__device__ __align__(16) unsigned char g_khi[(size_t)BH*Nn*256];
__device__ __align__(16) unsigned char g_vhi[(size_t)BH*Nn*256];

// ---------------- helpers ----------------
__device__ __forceinline__ uint32_t smem_u32(const void* p) {
    uint32_t a;
    asm("{ .reg .u64 t; cvta.to.shared.u64 t, %1; cvt.u32.u64 %0, t; }" : "=r"(a) : "l"(p));
    return a;
}
__device__ __forceinline__ uint32_t pack2h(float a, float b) {
    __half2 h = __floats2half2_rn(a, b);
    return *(uint32_t*)&h;
}
__device__ __forceinline__ void mma(float d[4], const uint32_t a[4], uint32_t b0, uint32_t b1) {
    asm volatile("mma.sync.aligned.m16n8k16.row.col.f32.f16.f16.f32 "
        "{%0,%1,%2,%3},{%4,%5,%6,%7},{%8,%9},{%0,%1,%2,%3};"
        : "+f"(d[0]), "+f"(d[1]), "+f"(d[2]), "+f"(d[3])
        : "r"(a[0]), "r"(a[1]), "r"(a[2]), "r"(a[3]), "r"(b0), "r"(b1));
}
__device__ __forceinline__ void ldsm4(uint32_t r[4], uint32_t a) {
    asm volatile("ldmatrix.sync.aligned.m8n8.x4.shared.b16 {%0,%1,%2,%3},[%4];"
        : "=r"(r[0]), "=r"(r[1]), "=r"(r[2]), "=r"(r[3]) : "r"(a));
}
__device__ __forceinline__ void ldsm4t(uint32_t r[4], uint32_t a) {
    asm volatile("ldmatrix.sync.aligned.m8n8.x4.trans.shared.b16 {%0,%1,%2,%3},[%4];"
        : "=r"(r[0]), "=r"(r[1]), "=r"(r[2]), "=r"(r[3]) : "r"(a));
}
#define CPA(dst, src) asm volatile("cp.async.cg.shared.global [%0],[%1],16;" :: "r"(dst), "l"(src))
#define CPC()  asm volatile("cp.async.commit_group;" ::: "memory")
#define CPW(n) asm volatile("cp.async.wait_group %0;" :: "n"(n) : "memory")

// ---------------- Q-hash only (also zero-inits g_keep) ----------------
__global__ void hashq_kernel(const float* __restrict__ q, const float* __restrict__ pd) {
    if (blockIdx.x == 0 && threadIdx.x < 64) g_keep[threadIdx.x] = 0;
    __shared__ float pds[Dd*NP];
    for (int i = threadIdx.x; i < Dd*NP; i += blockDim.x) pds[i] = pd[i];
    __syncthreads();
    int warp = threadIdx.x >> 5, lane = threadIdx.x & 31;
    int row = blockIdx.x * 8 + warp;               // q rows only: BH*Nn = 65536
    int n = row & (Nn-1), h = (row >> 11) & (Hh-1), b = row >> 15;
    float4 x = ((const float4*)(q + ((size_t)(b*Nn+n)*Hh + h)*Dd))[lane];
    int d0 = lane * 4;
    float acc[NP];
    #pragma unroll
    for (int p = 0; p < NP; p++)
        acc[p] = x.x*pds[(d0+0)*NP+p] + x.y*pds[(d0+1)*NP+p]
               + x.z*pds[(d0+2)*NP+p] + x.w*pds[(d0+3)*NP+p];
    #pragma unroll
    for (int p = 0; p < NP; p++)
        #pragma unroll
        for (int o = 16; o; o >>= 1) acc[p] += __shfl_xor_sync(0xffffffffu, acc[p], o);
    if (lane == 0) {
        int bin = 0;
        #pragma unroll
        for (int p = 0; p < NP; p++) bin |= ((acc[p] > 0.f) ? 1 : 0) << p;
        g_qhash[row] = bin ^ (bin >> 1);
    }
}

// ---------------- K/V prep: fp16 images (NO keep-zeroing) + fused K-hash ----
// 16 consecutive threads own one row. For K rows, each thread computes the
// 7 projection partial dots over its 8 elements; shfl-reduce over the
// 16-lane group; lane 0 writes g_khash.
__global__ void kvprep(const float* __restrict__ kg, const float* __restrict__ vg,
                       const float* __restrict__ pd) {
    __shared__ float pds[Dd*NP];
    for (int i = threadIdx.x; i < Dd*NP; i += 256) pds[i] = pd[i];
    __syncthreads();
    int idx = blockIdx.x * 256 + threadIdx.x;        // 2*BH*Nn*16
    int c = idx & 15;
    int row = (idx >> 4) & (Nn-1);
    int bh  = (idx >> 15) & (BH-1);
    int isv = idx >> 20;
    int h = bh & 15, b = bh >> 4;
    const float* src = isv ? vg : kg;
    const float4* sp = (const float4*)(src + ((size_t)(b*Nn+row)*Hh + h)*Dd) + c*2;
    float4 x0 = sp[0], x1 = sp[1];
    uint4 hv;
    hv.x = pack2h(x0.x, x0.y);
    hv.y = pack2h(x0.z, x0.w);
    hv.z = pack2h(x1.x, x1.y);
    hv.w = pack2h(x1.z, x1.w);
    size_t off = ((size_t)(bh*Nn + row))*256 + (size_t)((c ^ (row&7)) << 4);
    *(uint4*)((isv ? g_vhi : g_khi) + off) = hv;

    if (!isv) {
        float v[8] = {x0.x, x0.y, x0.z, x0.w, x1.x, x1.y, x1.z, x1.w};
        int d0 = c * 8;
        float acc[NP];
        #pragma unroll
        for (int p = 0; p < NP; p++) {
            float a = 0.f;
            #pragma unroll
            for (int j = 0; j < 8; j++) a += v[j] * pds[(d0+j)*NP + p];
            acc[p] = a;
        }
        #pragma unroll
        for (int p = 0; p < NP; p++)
            #pragma unroll
            for (int o = 8; o; o >>= 1)
                acc[p] += __shfl_xor_sync(0xffffffffu, acc[p], o);
        if (c == 0) {
            int bin = 0;
            #pragma unroll
            for (int p = 0; p < NP; p++) bin |= ((acc[p] > 0.f) ? 1 : 0) << p;
            g_khash[bh*Nn + row] = bin ^ (bin >> 1);
        }
    }
}

// ---------------- parallel stable counting sort per (b,h) + fused keep ------
// 128 threads; thread t owns elements [16t, 16t+16). u16 histogram
// pref[chunk][key] -> column scan (cross-chunk prefix per key) -> key
// prefix (below) -> stable scatter. keep[pos>>5] |= (qhash==khash at pos).
__global__ void __launch_bounds__(128) sort_kernel() {
    __shared__ int hs[Nn];
    __shared__ unsigned short pref[128][130];
    __shared__ int below[128];
    __shared__ int ks[64];
    int bh = blockIdx.x, base = bh * Nn;
    int t = threadIdx.x;
    for (int i = t; i < Nn; i += 128) hs[i] = g_qhash[base + i];
    #pragma unroll
    for (int k2 = 0; k2 < 128; k2++) pref[t][k2] = 0;
    if (t < 64) ks[t] = 0;
    __syncthreads();
    #pragma unroll
    for (int j = 0; j < 16; j++) pref[t][hs[t*16 + j]]++;
    __syncthreads();
    {   // thread t = key t: cross-chunk exclusive prefix + column total
        int run = 0;
        for (int c = 0; c < 128; c++) {
            int tmp = pref[c][t];
            pref[c][t] = (unsigned short)run;
            run += tmp;
        }
        below[t] = run;
    }
    __syncthreads();
    if (t == 0) {
        int run = 0;
        for (int k2 = 0; k2 < 128; k2++) { int tmp = below[k2]; below[k2] = run; run += tmp; }
    }
    __syncthreads();
    #pragma unroll
    for (int j = 0; j < 16; j++) {
        int i = t*16 + j;
        int k2 = hs[i];
        int pos = below[k2] + pref[t][k2];
        pref[t][k2]++;
        g_sidx[base + pos] = i;
        if (k2 == g_khash[base + pos]) ks[pos >> 5] = 1;
    }
    __syncthreads();
    if (t < 64 && ks[t]) atomicOr(&g_keep[t], 1);
}

// ---------------- HMMA flash attention (R14 structure + keep-skip) ----------
// fp16 single Q/K/P; Q pre-scaled by D^-0.5*log2(e); p = exp2(s) via
// ex2.approx.f16x2; l = P @ ones on the tensor core. keep==0 tiles skip
// all S MMAs/LDSM (s stays 0 -> p = 1, matching reference zeroed-K).
#define STAGE   65536           /* KHI 32K | V 32K */
#define OFF_V   32768
#define SMEMT   131072
#define ONES2   0x3C003C00u     /* fp16x2 {1,1} */

__global__ void __launch_bounds__(256, 1)
attn_kernel(const float* __restrict__ qg, float* __restrict__ out) {
    extern __shared__ __align__(16) unsigned char dsm[];
    uint32_t sb = smem_u32(dsm);
    int tid = threadIdx.x, warp = tid >> 5, lane = tid & 31;
    int qt = 15 - (int)blockIdx.x, h = blockIdx.y, b = blockIdx.z;
    int bh = b*Hh + h;

    // ---- stage Q (gathered rows, pre-scaled by sc*log2e, single fp16)
    {
        const float sc = 0.12751741f;   // 128^-0.5 * log2(e)
        #pragma unroll
        for (int it = 0; it < 8; it++) {
            int i = tid + it*256;
            int row = i >> 4, c = i & 15;
            int n = g_sidx[bh*Nn + qt*128 + row];
            const float4* qp = (const float4*)(qg + ((size_t)(b*Nn+n)*Hh + h)*Dd) + c*2;
            float4 x0 = qp[0], x1 = qp[1];
            uint4 hv;
            hv.x = pack2h(x0.x*sc, x0.y*sc);
            hv.y = pack2h(x0.z*sc, x0.w*sc);
            hv.z = pack2h(x1.x*sc, x1.y*sc);
            hv.w = pack2h(x1.z*sc, x1.w*sc);
            *(uint4*)(dsm + row*256 + ((c ^ (row&7)) << 4)) = hv;
        }
    }
    __syncthreads();

    // ---- extract Q fragments (A operand, 8 k-steps)
    uint32_t qh[8][4];
    {
        int qrow = 16*warp + (lane & 15);
        int cbit = lane >> 4, rsw = qrow & 7;
        uint32_t qb = sb + qrow*256;
        #pragma unroll
        for (int kk = 0; kk < 8; kk++)
            ldsm4(qh[kk], qb + (((2*kk + cbit) ^ rsw) << 4));
    }
    __syncthreads();

    size_t gbase = (size_t)(bh*Nn) * 256;

    // ---- prologue: stage 0 <- key tile 0 (128 keys: K 32KB, V 32KB)
    #pragma unroll
    for (int i2 = 0; i2 < 8; i2++) {
        int i = tid + i2*256;
        CPA(sb + i*16,         g_khi + gbase + i*16);
        CPA(sb + OFF_V + i*16, g_vhi + gbase + i*16);
    }
    CPC();

    float o[16][4];
    #pragma unroll
    for (int j = 0; j < 16; j++)
        #pragma unroll
        for (int e = 0; e < 4; e++) o[j][e] = 0.f;
    float lfr[4] = {0.f, 0.f, 0.f, 0.f};   // l = P @ ones (tensor-core)

    int keyl = lane & 15, ksw = keyl & 7, cbit = lane >> 4;
    int grA = qt*128 + 16*warp + (lane >> 2), grB = grA + 8;

    for (int kt = 0; kt <= qt; kt++) {
        CPW(0);
        __syncthreads();

        // prefetch next 128-key tile into the other stage
        if (kt < qt) {
            uint32_t st = sb + ((kt+1)&1)*STAGE;
            size_t gs = gbase + (size_t)(kt+1)*32768;
            #pragma unroll
            for (int i2 = 0; i2 < 8; i2++) {
                int i = tid + i2*256;
                CPA(st + i*16,         g_khi + gs + i*16);
                CPA(st + OFF_V + i*16, g_vhi + gs + i*16);
            }
            CPC();
        }

        bool dg = (kt == qt);
        int kp = g_keep[h*4 + (kt >> 2)];   // uniform per 128-key tile
        uint32_t stage = sb + (kt&1)*STAGE;

        #pragma unroll
        for (int sub = 0; sub < 2; sub++) {
            uint32_t stK = stage + sub*16384 + keyl*256;
            uint32_t stV = stage + OFF_V + sub*16384 + keyl*256;

            // ---- S = Q * K  (16x64 per warp, log2 domain); skip if dropped
            float s[8][4];
            #pragma unroll
            for (int j = 0; j < 8; j++)
                #pragma unroll
                for (int e = 0; e < 4; e++) s[j][e] = 0.f;

            if (kp) {
                #pragma unroll
                for (int kk = 0; kk < 8; kk++) {
                    #pragma unroll
                    for (int jp = 0; jp < 4; jp++) {
                        uint32_t kb[4];
                        ldsm4(kb, stK + jp*4096 + (((2*kk + cbit) ^ ksw) << 4));
                        mma(s[2*jp],   qh[kk], kb[0], kb[2]);
                        mma(s[2*jp+1], qh[kk], kb[1], kb[3]);
                    }
                }
            }

            // ---- softmax+pack fused: phi = ex2.approx.f16x2(pack2h(s))
            uint32_t phi[4][4];
            #pragma unroll
            for (int k2 = 0; k2 < 4; k2++) {
                #pragma unroll
                for (int u = 0; u < 4; u++) {
                    int j = 2*k2 + (u >> 1);
                    float a0 = s[j][(u & 1) ? 2 : 0];
                    float a1 = s[j][(u & 1) ? 3 : 1];
                    if (dg) {
                        int gc = kt*128 + sub*64 + 8*j + 2*(lane & 3);
                        int gr = (u & 1) ? grB : grA;
                        if (gc     > gr) a0 = -60000.f;   // exp2 -> 0
                        if (gc + 1 > gr) a1 = -60000.f;
                    }
                    uint32_t hh = pack2h(a0, a1);
                    asm("ex2.approx.f16x2 %0, %1;" : "=r"(phi[k2][u]) : "r"(hh));
                }
            }

            // ---- l += P @ ones ; O += P * V
            #pragma unroll
            for (int k2 = 0; k2 < 4; k2++) {
                mma(lfr, phi[k2], ONES2, ONES2);
                #pragma unroll
                for (int jp = 0; jp < 8; jp++) {
                    uint32_t vb[4];
                    ldsm4t(vb, stV + k2*4096 + (((2*jp + cbit) ^ ksw) << 4));
                    mma(o[2*jp],   phi[k2], vb[0], vb[1]);
                    mma(o[2*jp+1], phi[k2], vb[2], vb[3]);
                }
            }
        }
    }

    // ---- epilogue: normalize (l already per-row in lfr), scatter
    float iA = 1.f / lfr[0], iB = 1.f / lfr[2];
    int nA = g_sidx[bh*Nn + qt*128 + 16*warp + (lane >> 2)];
    int nB = g_sidx[bh*Nn + qt*128 + 16*warp + (lane >> 2) + 8];
    float* opA = out + ((size_t)(b*Nn+nA)*Hh + h)*Dd;
    float* opB = out + ((size_t)(b*Nn+nB)*Hh + h)*Dd;
    #pragma unroll
    for (int j = 0; j < 16; j++) {
        int col = 8*j + 2*(lane & 3);
        *(float2*)(opA + col) = make_float2(o[j][0]*iA, o[j][1]*iA);
        *(float2*)(opB + col) = make_float2(o[j][2]*iB, o[j][3]*iB);
    }
}

// ---------------- launch ----------------
extern "C" void kernel_launch(void* const* d_in, const int* in_sizes, int n_in,
                              void* d_out, int out_size) {
    const float* q  = (const float*)d_in[0];
    const float* k  = (const float*)d_in[1];
    const float* v  = (const float*)d_in[2];
    const float* pd = (const float*)d_in[3];
    float* out = (float*)d_out;

    hashq_kernel<<<8192, 256>>>(q, pd);
    kvprep<<<8192, 256>>>(k, v, pd);
    sort_kernel<<<BH, 128>>>();
    cudaFuncSetAttribute(attn_kernel, cudaFuncAttributeMaxDynamicSharedMemorySize, SMEMT);
    attn_kernel<<<dim3(16, Hh, Bb), 256, SMEMT>>>(q, out);
}

// round 17
// speedup vs baseline: 1.5501x; 1.0278x over previous
#include <cuda_runtime.h>
#include <cuda_fp16.h>
#include <math.h>
#include <stdint.h>

#define Bb 2
#define Hh 16
#define Nn 2048
#define Dd 128
#define NP 7
#define BH (Bb*Hh)

// ---------------- device scratch ----------------
__device__ int g_qhash[BH*Nn];
__device__ int g_khash[BH*Nn];
__device__ int g_sidx[BH*Nn];
__device__ int g_keep[64];
__device__ __align__(16) unsigned char g_khi[(size_t)BH*Nn*256];
__device__ __align__(16) unsigned char g_vhi[(size_t)BH*Nn*256];

// ---------------- helpers ----------------
__device__ __forceinline__ uint32_t smem_u32(const void* p) {
    uint32_t a;
    asm("{ .reg .u64 t; cvta.to.shared.u64 t, %1; cvt.u32.u64 %0, t; }" : "=r"(a) : "l"(p));
    return a;
}
__device__ __forceinline__ uint32_t pack2h(float a, float b) {
    __half2 h = __floats2half2_rn(a, b);
    return *(uint32_t*)&h;
}
__device__ __forceinline__ void mma(float d[4], const uint32_t a[4], uint32_t b0, uint32_t b1) {
    asm volatile("mma.sync.aligned.m16n8k16.row.col.f32.f16.f16.f32 "
        "{%0,%1,%2,%3},{%4,%5,%6,%7},{%8,%9},{%0,%1,%2,%3};"
        : "+f"(d[0]), "+f"(d[1]), "+f"(d[2]), "+f"(d[3])
        : "r"(a[0]), "r"(a[1]), "r"(a[2]), "r"(a[3]), "r"(b0), "r"(b1));
}
__device__ __forceinline__ void ldsm4(uint32_t r[4], uint32_t a) {
    asm volatile("ldmatrix.sync.aligned.m8n8.x4.shared.b16 {%0,%1,%2,%3},[%4];"
        : "=r"(r[0]), "=r"(r[1]), "=r"(r[2]), "=r"(r[3]) : "r"(a));
}
__device__ __forceinline__ void ldsm4t(uint32_t r[4], uint32_t a) {
    asm volatile("ldmatrix.sync.aligned.m8n8.x4.trans.shared.b16 {%0,%1,%2,%3},[%4];"
        : "=r"(r[0]), "=r"(r[1]), "=r"(r[2]), "=r"(r[3]) : "r"(a));
}
#define CPA(dst, src) asm volatile("cp.async.cg.shared.global [%0],[%1],16;" :: "r"(dst), "l"(src))
#define CPC()  asm volatile("cp.async.commit_group;" ::: "memory")
#define CPW(n) asm volatile("cp.async.wait_group %0;" :: "n"(n) : "memory")

// ---------------- K/V prep + BOTH hashes (fused) ----------------
// Grid covers 3 segments of BH*Nn rows x 16 threads:
//   sel 0 = K: fp16 image + k-hash;  sel 1 = V: fp16 image;  sel 2 = Q: q-hash.
// 16 consecutive threads own one row; hash partial dots shfl-reduced
// within the 16-lane group. Also zero-inits g_keep (block 0).
__global__ void kvprep(const float* __restrict__ kg, const float* __restrict__ vg,
                       const float* __restrict__ qg, const float* __restrict__ pd) {
    if (blockIdx.x == 0 && threadIdx.x < 64) g_keep[threadIdx.x] = 0;
    __shared__ float pds[Dd*NP];
    for (int i = threadIdx.x; i < Dd*NP; i += 256) pds[i] = pd[i];
    __syncthreads();
    int idx = blockIdx.x * 256 + threadIdx.x;        // 3*BH*Nn*16
    int c = idx & 15;
    int row = (idx >> 4) & (Nn-1);
    int bh  = (idx >> 15) & (BH-1);
    int sel = idx >> 20;                             // 0=K, 1=V, 2=Q
    int h = bh & 15, b = bh >> 4;
    const float* src = (sel == 0) ? kg : (sel == 1) ? vg : qg;
    const float4* sp = (const float4*)(src + ((size_t)(b*Nn+row)*Hh + h)*Dd) + c*2;
    float4 x0 = sp[0], x1 = sp[1];

    if (sel < 2) {
        uint4 hv;
        hv.x = pack2h(x0.x, x0.y);
        hv.y = pack2h(x0.z, x0.w);
        hv.z = pack2h(x1.x, x1.y);
        hv.w = pack2h(x1.z, x1.w);
        size_t off = ((size_t)(bh*Nn + row))*256 + (size_t)((c ^ (row&7)) << 4);
        *(uint4*)((sel ? g_vhi : g_khi) + off) = hv;
    }
    if (sel != 1) {
        float v[8] = {x0.x, x0.y, x0.z, x0.w, x1.x, x1.y, x1.z, x1.w};
        int d0 = c * 8;
        float acc[NP];
        #pragma unroll
        for (int p = 0; p < NP; p++) {
            float a = 0.f;
            #pragma unroll
            for (int j = 0; j < 8; j++) a += v[j] * pds[(d0+j)*NP + p];
            acc[p] = a;
        }
        #pragma unroll
        for (int p = 0; p < NP; p++)
            #pragma unroll
            for (int o = 8; o; o >>= 1)
                acc[p] += __shfl_xor_sync(0xffffffffu, acc[p], o);
        if (c == 0) {
            int bin = 0;
            #pragma unroll
            for (int p = 0; p < NP; p++) bin |= ((acc[p] > 0.f) ? 1 : 0) << p;
            ((sel == 0) ? g_khash : g_qhash)[bh*Nn + row] = bin ^ (bin >> 1);
        }
    }
}

// ---------------- parallel stable counting sort per (b,h) + fused keep ------
__global__ void __launch_bounds__(128) sort_kernel() {
    __shared__ int hs[Nn];
    __shared__ unsigned short pref[128][130];
    __shared__ int below[128];
    __shared__ int ks[64];
    int bh = blockIdx.x, base = bh * Nn;
    int t = threadIdx.x;
    for (int i = t; i < Nn; i += 128) hs[i] = g_qhash[base + i];
    #pragma unroll
    for (int k2 = 0; k2 < 128; k2++) pref[t][k2] = 0;
    if (t < 64) ks[t] = 0;
    __syncthreads();
    #pragma unroll
    for (int j = 0; j < 16; j++) pref[t][hs[t*16 + j]]++;
    __syncthreads();
    {
        int run = 0;
        for (int c = 0; c < 128; c++) {
            int tmp = pref[c][t];
            pref[c][t] = (unsigned short)run;
            run += tmp;
        }
        below[t] = run;
    }
    __syncthreads();
    if (t == 0) {
        int run = 0;
        for (int k2 = 0; k2 < 128; k2++) { int tmp = below[k2]; below[k2] = run; run += tmp; }
    }
    __syncthreads();
    #pragma unroll
    for (int j = 0; j < 16; j++) {
        int i = t*16 + j;
        int k2 = hs[i];
        int pos = below[k2] + pref[t][k2];
        pref[t][k2]++;
        g_sidx[base + pos] = i;
        if (k2 == g_khash[base + pos]) ks[pos >> 5] = 1;
    }
    __syncthreads();
    if (t < 64 && ks[t]) atomicOr(&g_keep[t], 1);
}

// ---------------- HMMA flash attention (staggered warp-groups) ----------
// fp16 single Q/K/P; Q pre-scaled by D^-0.5*log2(e); p = exp2(s) via
// ex2.approx.f16x2; l = P @ ones on the tensor core; keep-skip on S.
// Warps 0-3 process sub0->sub1; warps 4-7 process sub1->sub0 so half the
// SM is in the LDS-heavy S phase while half is in the tensor-heavy PV.
#define STAGE   65536           /* KHI 32K | V 32K */
#define OFF_V   32768
#define SMEMT   131072
#define ONES2   0x3C003C00u     /* fp16x2 {1,1} */

__global__ void __launch_bounds__(256, 1)
attn_kernel(const float* __restrict__ qg, float* __restrict__ out) {
    extern __shared__ __align__(16) unsigned char dsm[];
    uint32_t sb = smem_u32(dsm);
    int tid = threadIdx.x, warp = tid >> 5, lane = tid & 31;
    int qt = 15 - (int)blockIdx.x, h = blockIdx.y, b = blockIdx.z;
    int bh = b*Hh + h;

    // ---- stage Q (gathered rows, pre-scaled by sc*log2e, single fp16)
    {
        const float sc = 0.12751741f;   // 128^-0.5 * log2(e)
        #pragma unroll
        for (int it = 0; it < 8; it++) {
            int i = tid + it*256;
            int row = i >> 4, c = i & 15;
            int n = g_sidx[bh*Nn + qt*128 + row];
            const float4* qp = (const float4*)(qg + ((size_t)(b*Nn+n)*Hh + h)*Dd) + c*2;
            float4 x0 = qp[0], x1 = qp[1];
            uint4 hv;
            hv.x = pack2h(x0.x*sc, x0.y*sc);
            hv.y = pack2h(x0.z*sc, x0.w*sc);
            hv.z = pack2h(x1.x*sc, x1.y*sc);
            hv.w = pack2h(x1.z*sc, x1.w*sc);
            *(uint4*)(dsm + row*256 + ((c ^ (row&7)) << 4)) = hv;
        }
    }
    __syncthreads();

    // ---- extract Q fragments (A operand, 8 k-steps)
    uint32_t qh[8][4];
    {
        int qrow = 16*warp + (lane & 15);
        int cbit = lane >> 4, rsw = qrow & 7;
        uint32_t qb = sb + qrow*256;
        #pragma unroll
        for (int kk = 0; kk < 8; kk++)
            ldsm4(qh[kk], qb + (((2*kk + cbit) ^ rsw) << 4));
    }
    __syncthreads();

    size_t gbase = (size_t)(bh*Nn) * 256;

    // ---- prologue: stage 0 <- key tile 0 (128 keys: K 32KB, V 32KB)
    #pragma unroll
    for (int i2 = 0; i2 < 8; i2++) {
        int i = tid + i2*256;
        CPA(sb + i*16,         g_khi + gbase + i*16);
        CPA(sb + OFF_V + i*16, g_vhi + gbase + i*16);
    }
    CPC();

    float o[16][4];
    #pragma unroll
    for (int j = 0; j < 16; j++)
        #pragma unroll
        for (int e = 0; e < 4; e++) o[j][e] = 0.f;
    float lfr[4] = {0.f, 0.f, 0.f, 0.f};   // l = P @ ones (tensor-core)

    int keyl = lane & 15, ksw = keyl & 7, cbit = lane >> 4;
    int grA = qt*128 + 16*warp + (lane >> 2), grB = grA + 8;
    int sswap = (warp >> 2) & 1;            // warps 4-7 run subs reversed

    for (int kt = 0; kt <= qt; kt++) {
        CPW(0);
        __syncthreads();

        // prefetch next 128-key tile into the other stage
        if (kt < qt) {
            uint32_t st = sb + ((kt+1)&1)*STAGE;
            size_t gs = gbase + (size_t)(kt+1)*32768;
            #pragma unroll
            for (int i2 = 0; i2 < 8; i2++) {
                int i = tid + i2*256;
                CPA(st + i*16,         g_khi + gs + i*16);
                CPA(st + OFF_V + i*16, g_vhi + gs + i*16);
            }
            CPC();
        }

        bool dg = (kt == qt);
        int kp = g_keep[h*4 + (kt >> 2)];   // uniform per 128-key tile
        uint32_t stage = sb + (kt&1)*STAGE;

        #pragma unroll
        for (int sx = 0; sx < 2; sx++) {
            int sub = sx ^ sswap;
            uint32_t stK = stage + sub*16384 + keyl*256;
            uint32_t stV = stage + OFF_V + sub*16384 + keyl*256;

            // ---- S = Q * K  (16x64 per warp, log2 domain); skip if dropped
            float s[8][4];
            #pragma unroll
            for (int j = 0; j < 8; j++)
                #pragma unroll
                for (int e = 0; e < 4; e++) s[j][e] = 0.f;

            if (kp) {
                #pragma unroll
                for (int kk = 0; kk < 8; kk++) {
                    #pragma unroll
                    for (int jp = 0; jp < 4; jp++) {
                        uint32_t kb[4];
                        ldsm4(kb, stK + jp*4096 + (((2*kk + cbit) ^ ksw) << 4));
                        mma(s[2*jp],   qh[kk], kb[0], kb[2]);
                        mma(s[2*jp+1], qh[kk], kb[1], kb[3]);
                    }
                }
            }

            // ---- softmax+pack fused: phi = ex2.approx.f16x2(pack2h(s))
            uint32_t phi[4][4];
            #pragma unroll
            for (int k2 = 0; k2 < 4; k2++) {
                #pragma unroll
                for (int u = 0; u < 4; u++) {
                    int j = 2*k2 + (u >> 1);
                    float a0 = s[j][(u & 1) ? 2 : 0];
                    float a1 = s[j][(u & 1) ? 3 : 1];
                    if (dg) {
                        int gc = kt*128 + sub*64 + 8*j + 2*(lane & 3);
                        int gr = (u & 1) ? grB : grA;
                        if (gc     > gr) a0 = -60000.f;   // exp2 -> 0
                        if (gc + 1 > gr) a1 = -60000.f;
                    }
                    uint32_t hh = pack2h(a0, a1);
                    asm("ex2.approx.f16x2 %0, %1;" : "=r"(phi[k2][u]) : "r"(hh));
                }
            }

            // ---- l += P @ ones ; O += P * V
            #pragma unroll
            for (int k2 = 0; k2 < 4; k2++) {
                mma(lfr, phi[k2], ONES2, ONES2);
                #pragma unroll
                for (int jp = 0; jp < 8; jp++) {
                    uint32_t vb[4];
                    ldsm4t(vb, stV + k2*4096 + (((2*jp + cbit) ^ ksw) << 4));
                    mma(o[2*jp],   phi[k2], vb[0], vb[1]);
                    mma(o[2*jp+1], phi[k2], vb[2], vb[3]);
                }
            }
        }
    }

    // ---- epilogue: normalize (l already per-row in lfr), scatter
    float iA = 1.f / lfr[0], iB = 1.f / lfr[2];
    int nA = g_sidx[bh*Nn + qt*128 + 16*warp + (lane >> 2)];
    int nB = g_sidx[bh*Nn + qt*128 + 16*warp + (lane >> 2) + 8];
    float* opA = out + ((size_t)(b*Nn+nA)*Hh + h)*Dd;
    float* opB = out + ((size_t)(b*Nn+nB)*Hh + h)*Dd;
    #pragma unroll
    for (int j = 0; j < 16; j++) {
        int col = 8*j + 2*(lane & 3);
        *(float2*)(opA + col) = make_float2(o[j][0]*iA, o[j][1]*iA);
        *(float2*)(opB + col) = make_float2(o[j][2]*iB, o[j][3]*iB);
    }
}

// ---------------- launch ----------------
extern "C" void kernel_launch(void* const* d_in, const int* in_sizes, int n_in,
                              void* d_out, int out_size) {
    const float* q  = (const float*)d_in[0];
    const float* k  = (const float*)d_in[1];
    const float* v  = (const float*)d_in[2];
    const float* pd = (const float*)d_in[3];
    float* out = (float*)d_out;

    kvprep<<<12288, 256>>>(k, v, q, pd);
    sort_kernel<<<BH, 128>>>();
    cudaFuncSetAttribute(attn_kernel, cudaFuncAttributeMaxDynamicSharedMemorySize, SMEMT);
    attn_kernel<<<dim3(16, Hh, Bb), 256, SMEMT>>>(q, out);
}